// round 3
// baseline (speedup 1.0000x reference)
#include <cuda_runtime.h>

#define BATCH 16
#define NPTS  2048
#define CDIM  64
#define ODIM  64
#define KNN   20
#define ROWS_TOTAL (BATCH*NPTS)   // 32768
#define NEG_INF (-3.402823466e38f)
#define FULLMASK 0xffffffffu

// ---------------- scratch (static device globals; no allocation) ----------------
__device__ float  g_xx[ROWS_TOTAL];
__device__ float  g_hc[ROWS_TOTAL*ODIM];
__device__ float  g_hn[ROWS_TOTAL*ODIM];
__device__ int    g_idx[ROWS_TOTAL*KNN];
__device__ float  g_mmax[ROWS_TOTAL*ODIM];
__device__ float  g_mmin[ROWS_TOTAL*ODIM];
__device__ double g_sum[ODIM];
__device__ double g_sumsq[ODIM];
__device__ float  g_scale[ODIM];
__device__ float  g_shift[ODIM];

// ---------------- K0: zero stats accumulators (graph replay safe) ----------------
__global__ void k_zero() {
    int t = threadIdx.x;
    if (t < ODIM) { g_sum[t] = 0.0; g_sumsq[t] = 0.0; }
}

// ---------------- K1: row squared norms ----------------
__global__ void k_xx(const float* __restrict__ x) {
    int row  = blockIdx.x * 4 + (threadIdx.x >> 5);
    int lane = threadIdx.x & 31;
    const float2* x2 = (const float2*)(x + (size_t)row * CDIM);
    float2 v = x2[lane];
    float s = v.x * v.x + v.y * v.y;
    #pragma unroll
    for (int o = 16; o; o >>= 1) s += __shfl_down_sync(FULLMASK, s, o);
    if (lane == 0) g_xx[row] = s;
}

// ---------------- K2: hc = x@W1^T + b, hn = x@W2^T  (32 rows/block) ----------------
__global__ void k_hchn(const float* __restrict__ x, const float* __restrict__ W,
                       const float* __restrict__ bias) {
    extern __shared__ float sm[];
    float4* Wt4 = (float4*)sm;          // [128*17]
    float4* rX4 = Wt4 + 128 * 17;       // [32*16]
    int t = threadIdx.x;
    int rowbase = blockIdx.x * 32;
    const float4* Wg4 = (const float4*)W;
    const float4* xg4 = (const float4*)x;

    #pragma unroll 2
    for (int li = t; li < 128 * 16; li += 256) {
        int cq = li & 15, p = li >> 4;
        Wt4[p * 17 + cq] = (p < 64) ? Wg4[p * 32 + cq] : Wg4[(p - 64) * 32 + 16 + cq];
    }
    for (int li = t; li < 32 * 16; li += 256) {
        int cq = li & 15, r = li >> 4;
        rX4[r * 16 + cq] = xg4[(size_t)(rowbase + r) * 16 + cq];
    }
    __syncthreads();

    int warp = t >> 5, j = t & 31;
    int rl0 = warp * 4;
    float acc[4][4];
    #pragma unroll
    for (int r = 0; r < 4; r++)
        #pragma unroll
        for (int q = 0; q < 4; q++) acc[r][q] = 0.f;

    #pragma unroll
    for (int cq = 0; cq < 16; cq++) {
        float4 c0 = Wt4[(j     ) * 17 + cq];
        float4 c1 = Wt4[(j + 32) * 17 + cq];
        float4 c2 = Wt4[(j + 64) * 17 + cq];
        float4 c3 = Wt4[(j + 96) * 17 + cq];
        #pragma unroll
        for (int r = 0; r < 4; r++) {
            float4 rv = rX4[(rl0 + r) * 16 + cq];
            acc[r][0] = fmaf(rv.w, c0.w, fmaf(rv.z, c0.z, fmaf(rv.y, c0.y, fmaf(rv.x, c0.x, acc[r][0]))));
            acc[r][1] = fmaf(rv.w, c1.w, fmaf(rv.z, c1.z, fmaf(rv.y, c1.y, fmaf(rv.x, c1.x, acc[r][1]))));
            acc[r][2] = fmaf(rv.w, c2.w, fmaf(rv.z, c2.z, fmaf(rv.y, c2.y, fmaf(rv.x, c2.x, acc[r][2]))));
            acc[r][3] = fmaf(rv.w, c3.w, fmaf(rv.z, c3.z, fmaf(rv.y, c3.y, fmaf(rv.x, c3.x, acc[r][3]))));
        }
    }
    #pragma unroll
    for (int q = 0; q < 4; q++) {
        int p = j + 32 * q;
        float bv = (p < 64) ? bias[p] : 0.f;
        #pragma unroll
        for (int r = 0; r < 4; r++) {
            int row = rowbase + rl0 + r;
            if (p < 64) g_hc[(size_t)row * 64 + p] = acc[r][q] + bv;
            else        g_hn[(size_t)row * 64 + (p - 64)] = acc[r][q];
        }
    }
}

// ---------------- K3: fused Gram + top-20 per row (register-resident top-k) ----------------
// block: 256 threads = 8 warps, 32 rows (4 rows/warp), col tiles of 128.
// Top-20 list for each of the warp's 4 rows lives distributed across lanes:
// lane j (j<20) holds element j of the descending-sorted list (value + index).
__global__ void k_topk(const float* __restrict__ x) {
    extern __shared__ float sm[];
    float4* rX4  = (float4*)sm;              // [32*16]
    float4* cX4  = rX4 + 32 * 16;            // [128*17]
    float*  xxc  = (float*)(cX4 + 128 * 17); // [128]

    int t = threadIdx.x;
    int b = blockIdx.y;
    int rowbase = b * NPTS + blockIdx.x * 32;
    const float4* xg4 = (const float4*)x;

    for (int li = t; li < 32 * 16; li += 256) {
        int cq = li & 15, r = li >> 4;
        rX4[r * 16 + cq] = xg4[(size_t)(rowbase + r) * 16 + cq];
    }

    int warp = t >> 5, j = t & 31;
    int rl0 = warp * 4;
    bool inlist = (j < KNN);

    // register-resident top-k lists (per lane: element j of each row's list)
    float lv[4]; int lidx[4]; float th[4];
    #pragma unroll
    for (int r = 0; r < 4; r++) { lv[r] = NEG_INF; lidx[r] = 0; th[r] = NEG_INF; }

    for (int ct = 0; ct < 16; ct++) {
        int cb = ct * 128;
        __syncthreads();
        #pragma unroll 2
        for (int li = t; li < 128 * 16; li += 256) {
            int cq = li & 15, col = li >> 4;
            cX4[col * 17 + cq] = xg4[(size_t)(b * NPTS + cb + col) * 16 + cq];
        }
        if (t < 128) xxc[t] = g_xx[b * NPTS + cb + t];
        __syncthreads();

        float acc[4][4];
        #pragma unroll
        for (int r = 0; r < 4; r++)
            #pragma unroll
            for (int q = 0; q < 4; q++) acc[r][q] = 0.f;

        #pragma unroll
        for (int cq = 0; cq < 16; cq++) {
            float4 c0 = cX4[(j     ) * 17 + cq];
            float4 c1 = cX4[(j + 32) * 17 + cq];
            float4 c2 = cX4[(j + 64) * 17 + cq];
            float4 c3 = cX4[(j + 96) * 17 + cq];
            #pragma unroll
            for (int r = 0; r < 4; r++) {
                float4 rv = rX4[(rl0 + r) * 16 + cq];
                acc[r][0] = fmaf(rv.w, c0.w, fmaf(rv.z, c0.z, fmaf(rv.y, c0.y, fmaf(rv.x, c0.x, acc[r][0]))));
                acc[r][1] = fmaf(rv.w, c1.w, fmaf(rv.z, c1.z, fmaf(rv.y, c1.y, fmaf(rv.x, c1.x, acc[r][1]))));
                acc[r][2] = fmaf(rv.w, c2.w, fmaf(rv.z, c2.z, fmaf(rv.y, c2.y, fmaf(rv.x, c2.x, acc[r][2]))));
                acc[r][3] = fmaf(rv.w, c3.w, fmaf(rv.z, c3.z, fmaf(rv.y, c3.y, fmaf(rv.x, c3.x, acc[r][3]))));
            }
        }

        // per-tile candidate xx terms (independent of r)
        float xq0 = xxc[j], xq1 = xxc[j + 32], xq2 = xxc[j + 64], xq3 = xxc[j + 96];

        #pragma unroll
        for (int r = 0; r < 4; r++) {
            float cnd[4];
            cnd[0] = fmaf(-2.f, acc[r][0], xq0);
            cnd[1] = fmaf(-2.f, acc[r][1], xq1);
            cnd[2] = fmaf(-2.f, acc[r][2], xq2);
            cnd[3] = fmaf(-2.f, acc[r][3], xq3);
            #pragma unroll
            for (int q = 0; q < 4; q++) {
                float cand = cnd[q];
                int   col  = cb + j + 32 * q;
                unsigned mask = __ballot_sync(FULLMASK, cand > th[r]);
                while (mask) {
                    int src = __ffs(mask) - 1; mask &= mask - 1;
                    float val = __shfl_sync(FULLMASK, cand, src);
                    int   ci  = __shfl_sync(FULLMASK, col,  src);
                    if (val > th[r]) {   // warp-uniform
                        // stable insertion: position = #elements >= val
                        unsigned ge = __ballot_sync(FULLMASK, inlist && (lv[r] >= val));
                        int pos = __popc(ge);
                        float pv = __shfl_up_sync(FULLMASK, lv[r], 1);
                        int   pi = __shfl_up_sync(FULLMASK, lidx[r], 1);
                        if (inlist) {
                            if (j == pos)     { lv[r] = val; lidx[r] = ci; }
                            else if (j > pos) { lv[r] = pv;  lidx[r] = pi; }
                        }
                        th[r] = __shfl_sync(FULLMASK, lv[r], KNN - 1);
                    }
                }
            }
        }
    }

    // write out indices: lane j<20 holds element j of each row's list
    #pragma unroll
    for (int r = 0; r < 4; r++) {
        int row = rowbase + rl0 + r;
        if (inlist) g_idx[(size_t)row * KNN + j] = lidx[r];
    }
}

// ---------------- K4: gather + BN stats + per-(row,o) max/min ----------------
__global__ void k_stats() {
    __shared__ int   sidx[32 * KNN];
    __shared__ float ssum[4][64];
    __shared__ float sssq[4][64];
    int tx = threadIdx.x, ty = threadIdx.y;
    int t = ty * 64 + tx;
    int rowbase = blockIdx.x * 32;
    int bb = (rowbase >> 11) << 11;

    for (int i = t; i < 32 * KNN; i += 256) sidx[i] = g_idx[(size_t)rowbase * KNN + i];
    __syncthreads();

    float sum = 0.f, ssq = 0.f;
    for (int ri = ty; ri < 32; ri += 4) {
        int row = rowbase + ri;
        float hcv = g_hc[(size_t)row * 64 + tx];
        float mx = NEG_INF, mn = -NEG_INF;
        #pragma unroll
        for (int k = 0; k < KNN; k++) {
            int jj = sidx[ri * KNN + k];
            float v = hcv + g_hn[(size_t)(bb + jj) * 64 + tx];
            sum += v; ssq = fmaf(v, v, ssq);
            mx = fmaxf(mx, v); mn = fminf(mn, v);
        }
        g_mmax[(size_t)row * 64 + tx] = mx;
        g_mmin[(size_t)row * 64 + tx] = mn;
    }
    ssum[ty][tx] = sum; sssq[ty][tx] = ssq;
    __syncthreads();
    if (ty == 0) {
        float s = ssum[0][tx] + ssum[1][tx] + ssum[2][tx] + ssum[3][tx];
        float q = sssq[0][tx] + sssq[1][tx] + sssq[2][tx] + sssq[3][tx];
        atomicAdd(&g_sum[tx],   (double)s);
        atomicAdd(&g_sumsq[tx], (double)q);
    }
}

// ---------------- K5: finalize BN scale/shift ----------------
__global__ void k_final(const float* __restrict__ gamma, const float* __restrict__ beta) {
    int o = threadIdx.x;
    if (o < ODIM) {
        double cnt  = (double)ROWS_TOTAL * KNN;
        double mean = g_sum[o] / cnt;
        double var  = g_sumsq[o] / cnt - mean * mean;
        float sc = gamma[o] * rsqrtf((float)var + 1e-5f);
        g_scale[o] = sc;
        g_shift[o] = beta[o] - (float)mean * sc;
    }
}

// ---------------- K6: apply affine + LeakyReLU + transpose to [B,O,N] ----------------
__global__ void k_out(float* __restrict__ out) {
    __shared__ float smt[64][65];
    int tx = threadIdx.x, ty = threadIdx.y;   // block (64,4)
    int nb = blockIdx.x * 64;
    int b  = blockIdx.y;
    float sc = g_scale[tx], sh = g_shift[tx];
    #pragma unroll
    for (int i = 0; i < 16; i++) {
        int nl = ty + 4 * i;
        size_t rowoff = (size_t)(b * NPTS + nb + nl) * 64 + tx;
        float m = (sc >= 0.f) ? g_mmax[rowoff] : g_mmin[rowoff];
        float y = fmaf(m, sc, sh);
        y = (y >= 0.f) ? y : 0.2f * y;
        smt[nl][tx] = y;
    }
    __syncthreads();
    #pragma unroll
    for (int i = 0; i < 16; i++) {
        int o = ty + 4 * i;
        out[((size_t)(b * 64 + o)) * NPTS + nb + tx] = smt[tx][o];
    }
}

extern "C" void kernel_launch(void* const* d_in, const int* in_sizes, int n_in,
                              void* d_out, int out_size) {
    const float* x     = (const float*)d_in[0];
    const float* W     = (const float*)d_in[1];
    const float* bias  = (const float*)d_in[2];
    const float* gamma = (const float*)d_in[3];
    const float* beta  = (const float*)d_in[4];
    float* out = (float*)d_out;

    k_zero<<<1, 64>>>();
    k_xx<<<ROWS_TOTAL / 4, 128>>>(x);
    k_hchn<<<ROWS_TOTAL / 32, 256, (128 * 17 + 32 * 16) * 16>>>(x, W, bias);
    k_topk<<<dim3(NPTS / 32, BATCH), 256,
             (32 * 16 + 128 * 17) * 16 + 128 * 4>>>(x);
    k_stats<<<ROWS_TOTAL / 32, dim3(64, 4)>>>();
    k_final<<<1, 64>>>(gamma, beta);
    k_out<<<dim3(NPTS / 64, BATCH), dim3(64, 4)>>>(out);
}

// round 4
// speedup vs baseline: 1.1667x; 1.1667x over previous
#include <cuda_runtime.h>

#define BATCH 16
#define NPTS  2048
#define CDIM  64
#define ODIM  64
#define KNN   20
#define ROWS_TOTAL (BATCH*NPTS)   // 32768
#define NEG_INF (-3.402823466e38f)
#define FULLMASK 0xffffffffu

// ---------------- scratch (static device globals; no allocation) ----------------
__device__ float  g_xx[ROWS_TOTAL];
__device__ float  g_hc[ROWS_TOTAL*ODIM];
__device__ float  g_hn[ROWS_TOTAL*ODIM];
__device__ int    g_idx[ROWS_TOTAL*KNN];
__device__ float  g_mmax[ROWS_TOTAL*ODIM];
__device__ float  g_mmin[ROWS_TOTAL*ODIM];
__device__ double g_sum[ODIM];
__device__ double g_sumsq[ODIM];
__device__ float  g_scale[ODIM];
__device__ float  g_shift[ODIM];

// ---------------- K0: zero stats accumulators (graph replay safe) ----------------
__global__ void k_zero() {
    int t = threadIdx.x;
    if (t < ODIM) { g_sum[t] = 0.0; g_sumsq[t] = 0.0; }
}

// ---------------- K1: row squared norms ----------------
__global__ void k_xx(const float* __restrict__ x) {
    int row  = blockIdx.x * 4 + (threadIdx.x >> 5);
    int lane = threadIdx.x & 31;
    const float2* x2 = (const float2*)(x + (size_t)row * CDIM);
    float2 v = x2[lane];
    float s = v.x * v.x + v.y * v.y;
    #pragma unroll
    for (int o = 16; o; o >>= 1) s += __shfl_down_sync(FULLMASK, s, o);
    if (lane == 0) g_xx[row] = s;
}

// ---------------- K2: hc = x@W1^T + b, hn = x@W2^T  (32 rows/block) ----------------
__global__ void k_hchn(const float* __restrict__ x, const float* __restrict__ W,
                       const float* __restrict__ bias) {
    extern __shared__ float sm[];
    float4* Wt4 = (float4*)sm;          // [128*17]
    float4* rX4 = Wt4 + 128 * 17;       // [32*16]
    int t = threadIdx.x;
    int rowbase = blockIdx.x * 32;
    const float4* Wg4 = (const float4*)W;
    const float4* xg4 = (const float4*)x;

    #pragma unroll 2
    for (int li = t; li < 128 * 16; li += 256) {
        int cq = li & 15, p = li >> 4;
        Wt4[p * 17 + cq] = (p < 64) ? Wg4[p * 32 + cq] : Wg4[(p - 64) * 32 + 16 + cq];
    }
    for (int li = t; li < 32 * 16; li += 256) {
        int cq = li & 15, r = li >> 4;
        rX4[r * 16 + cq] = xg4[(size_t)(rowbase + r) * 16 + cq];
    }
    __syncthreads();

    int warp = t >> 5, j = t & 31;
    int rl0 = warp * 4;
    float acc[4][4];
    #pragma unroll
    for (int r = 0; r < 4; r++)
        #pragma unroll
        for (int q = 0; q < 4; q++) acc[r][q] = 0.f;

    #pragma unroll
    for (int cq = 0; cq < 16; cq++) {
        float4 c0 = Wt4[(j     ) * 17 + cq];
        float4 c1 = Wt4[(j + 32) * 17 + cq];
        float4 c2 = Wt4[(j + 64) * 17 + cq];
        float4 c3 = Wt4[(j + 96) * 17 + cq];
        #pragma unroll
        for (int r = 0; r < 4; r++) {
            float4 rv = rX4[(rl0 + r) * 16 + cq];
            acc[r][0] = fmaf(rv.w, c0.w, fmaf(rv.z, c0.z, fmaf(rv.y, c0.y, fmaf(rv.x, c0.x, acc[r][0]))));
            acc[r][1] = fmaf(rv.w, c1.w, fmaf(rv.z, c1.z, fmaf(rv.y, c1.y, fmaf(rv.x, c1.x, acc[r][1]))));
            acc[r][2] = fmaf(rv.w, c2.w, fmaf(rv.z, c2.z, fmaf(rv.y, c2.y, fmaf(rv.x, c2.x, acc[r][2]))));
            acc[r][3] = fmaf(rv.w, c3.w, fmaf(rv.z, c3.z, fmaf(rv.y, c3.y, fmaf(rv.x, c3.x, acc[r][3]))));
        }
    }
    #pragma unroll
    for (int q = 0; q < 4; q++) {
        int p = j + 32 * q;
        float bv = (p < 64) ? bias[p] : 0.f;
        #pragma unroll
        for (int r = 0; r < 4; r++) {
            int row = rowbase + rl0 + r;
            if (p < 64) g_hc[(size_t)row * 64 + p] = acc[r][q] + bv;
            else        g_hn[(size_t)row * 64 + (p - 64)] = acc[r][q];
        }
    }
}

// ---------------- K3: fused Gram + top-20 per row (register-resident top-k) ----------------
// block: 256 threads = 8 warps, 32 rows (4 rows/warp), col tiles of 128.
// Top-20 list distributed across lanes: lane j (j<20) holds element j (desc sorted).
// Insert path uses a stale-threshold scheme: the threshold th is refreshed only
// once per 32-candidate batch. A stale (lower) th only admits extra candidates
// whose insertion position pos >= 20, which writes nothing -> correctness intact.
__global__ void __launch_bounds__(256, 4) k_topk(const float* __restrict__ x) {
    extern __shared__ float sm[];
    float4* rX4  = (float4*)sm;              // [32*16]
    float4* cX4  = rX4 + 32 * 16;            // [128*17]
    float*  xxc  = (float*)(cX4 + 128 * 17); // [128]

    int t = threadIdx.x;
    int b = blockIdx.y;
    int rowbase = b * NPTS + blockIdx.x * 32;
    const float4* xg4 = (const float4*)x;

    for (int li = t; li < 32 * 16; li += 256) {
        int cq = li & 15, r = li >> 4;
        rX4[r * 16 + cq] = xg4[(size_t)(rowbase + r) * 16 + cq];
    }

    int warp = t >> 5, j = t & 31;
    int rl0 = warp * 4;
    bool inlist = (j < KNN);

    float lv[4]; int lidx[4]; float th[4];
    #pragma unroll
    for (int r = 0; r < 4; r++) { lv[r] = NEG_INF; lidx[r] = 0; th[r] = NEG_INF; }

    for (int ct = 0; ct < 16; ct++) {
        int cb = ct * 128;
        __syncthreads();
        #pragma unroll 2
        for (int li = t; li < 128 * 16; li += 256) {
            int cq = li & 15, col = li >> 4;
            cX4[col * 17 + cq] = xg4[(size_t)(b * NPTS + cb + col) * 16 + cq];
        }
        if (t < 128) xxc[t] = g_xx[b * NPTS + cb + t];
        __syncthreads();

        float acc[4][4];
        #pragma unroll
        for (int r = 0; r < 4; r++)
            #pragma unroll
            for (int q = 0; q < 4; q++) acc[r][q] = 0.f;

        #pragma unroll
        for (int cq = 0; cq < 16; cq++) {
            float4 c0 = cX4[(j     ) * 17 + cq];
            float4 c1 = cX4[(j + 32) * 17 + cq];
            float4 c2 = cX4[(j + 64) * 17 + cq];
            float4 c3 = cX4[(j + 96) * 17 + cq];
            #pragma unroll
            for (int r = 0; r < 4; r++) {
                float4 rv = rX4[(rl0 + r) * 16 + cq];
                acc[r][0] = fmaf(rv.w, c0.w, fmaf(rv.z, c0.z, fmaf(rv.y, c0.y, fmaf(rv.x, c0.x, acc[r][0]))));
                acc[r][1] = fmaf(rv.w, c1.w, fmaf(rv.z, c1.z, fmaf(rv.y, c1.y, fmaf(rv.x, c1.x, acc[r][1]))));
                acc[r][2] = fmaf(rv.w, c2.w, fmaf(rv.z, c2.z, fmaf(rv.y, c2.y, fmaf(rv.x, c2.x, acc[r][2]))));
                acc[r][3] = fmaf(rv.w, c3.w, fmaf(rv.z, c3.z, fmaf(rv.y, c3.y, fmaf(rv.x, c3.x, acc[r][3]))));
            }
        }

        float xq0 = xxc[j], xq1 = xxc[j + 32], xq2 = xxc[j + 64], xq3 = xxc[j + 96];

        #pragma unroll
        for (int r = 0; r < 4; r++) {
            float cnd0 = fmaf(-2.f, acc[r][0], xq0);
            float cnd1 = fmaf(-2.f, acc[r][1], xq1);
            float cnd2 = fmaf(-2.f, acc[r][2], xq2);
            float cnd3 = fmaf(-2.f, acc[r][3], xq3);
            // row-tile prefilter: skip all 4 batches when nothing can pass
            float rmax = fmaxf(fmaxf(cnd0, cnd1), fmaxf(cnd2, cnd3));
            if (__ballot_sync(FULLMASK, rmax > th[r]) == 0u) continue;

            #pragma unroll
            for (int q = 0; q < 4; q++) {
                float cand = (q == 0) ? cnd0 : (q == 1) ? cnd1 : (q == 2) ? cnd2 : cnd3;
                int   col  = cb + j + 32 * q;
                unsigned mask = __ballot_sync(FULLMASK, cand > th[r]);
                while (mask) {
                    int src = __ffs(mask) - 1; mask &= mask - 1;
                    float val = __shfl_sync(FULLMASK, cand, src);
                    int   ci  = __shfl_sync(FULLMASK, col,  src);
                    // stable insertion: position = #elements >= val; pos>=20 -> no-op
                    unsigned ge = __ballot_sync(FULLMASK, inlist && (lv[r] >= val));
                    int pos = __popc(ge);
                    float pv = __shfl_up_sync(FULLMASK, lv[r], 1);
                    int   pi = __shfl_up_sync(FULLMASK, lidx[r], 1);
                    if (inlist) {
                        if (j == pos)     { lv[r] = val; lidx[r] = ci; }
                        else if (j > pos) { lv[r] = pv;  lidx[r] = pi; }
                    }
                }
                th[r] = __shfl_sync(FULLMASK, lv[r], KNN - 1);
            }
        }
    }

    #pragma unroll
    for (int r = 0; r < 4; r++) {
        int row = rowbase + rl0 + r;
        if (inlist) g_idx[(size_t)row * KNN + j] = lidx[r];
    }
}

// ---------------- K4: gather + BN stats + per-(row,o) max/min ----------------
__global__ void k_stats() {
    __shared__ int   sidx[32 * KNN];
    __shared__ float ssum[4][64];
    __shared__ float sssq[4][64];
    int tx = threadIdx.x, ty = threadIdx.y;
    int t = ty * 64 + tx;
    int rowbase = blockIdx.x * 32;
    int bb = (rowbase >> 11) << 11;

    for (int i = t; i < 32 * KNN; i += 256) sidx[i] = g_idx[(size_t)rowbase * KNN + i];
    __syncthreads();

    float sum = 0.f, ssq = 0.f;
    for (int ri = ty; ri < 32; ri += 4) {
        int row = rowbase + ri;
        float hcv = g_hc[(size_t)row * 64 + tx];
        float mx = NEG_INF, mn = -NEG_INF;
        #pragma unroll
        for (int k = 0; k < KNN; k++) {
            int jj = sidx[ri * KNN + k];
            float v = hcv + g_hn[(size_t)(bb + jj) * 64 + tx];
            sum += v; ssq = fmaf(v, v, ssq);
            mx = fmaxf(mx, v); mn = fminf(mn, v);
        }
        g_mmax[(size_t)row * 64 + tx] = mx;
        g_mmin[(size_t)row * 64 + tx] = mn;
    }
    ssum[ty][tx] = sum; sssq[ty][tx] = ssq;
    __syncthreads();
    if (ty == 0) {
        float s = ssum[0][tx] + ssum[1][tx] + ssum[2][tx] + ssum[3][tx];
        float q = sssq[0][tx] + sssq[1][tx] + sssq[2][tx] + sssq[3][tx];
        atomicAdd(&g_sum[tx],   (double)s);
        atomicAdd(&g_sumsq[tx], (double)q);
    }
}

// ---------------- K5: finalize BN scale/shift ----------------
__global__ void k_final(const float* __restrict__ gamma, const float* __restrict__ beta) {
    int o = threadIdx.x;
    if (o < ODIM) {
        double cnt  = (double)ROWS_TOTAL * KNN;
        double mean = g_sum[o] / cnt;
        double var  = g_sumsq[o] / cnt - mean * mean;
        float sc = gamma[o] * rsqrtf((float)var + 1e-5f);
        g_scale[o] = sc;
        g_shift[o] = beta[o] - (float)mean * sc;
    }
}

// ---------------- K6: apply affine + LeakyReLU + transpose to [B,O,N] ----------------
__global__ void k_out(float* __restrict__ out) {
    __shared__ float smt[64][65];
    int tx = threadIdx.x, ty = threadIdx.y;   // block (64,4)
    int nb = blockIdx.x * 64;
    int b  = blockIdx.y;
    float sc = g_scale[tx], sh = g_shift[tx];
    #pragma unroll
    for (int i = 0; i < 16; i++) {
        int nl = ty + 4 * i;
        size_t rowoff = (size_t)(b * NPTS + nb + nl) * 64 + tx;
        float m = (sc >= 0.f) ? g_mmax[rowoff] : g_mmin[rowoff];
        float y = fmaf(m, sc, sh);
        y = (y >= 0.f) ? y : 0.2f * y;
        smt[nl][tx] = y;
    }
    __syncthreads();
    #pragma unroll
    for (int i = 0; i < 16; i++) {
        int o = ty + 4 * i;
        out[((size_t)(b * 64 + o)) * NPTS + nb + tx] = smt[tx][o];
    }
}

extern "C" void kernel_launch(void* const* d_in, const int* in_sizes, int n_in,
                              void* d_out, int out_size) {
    const float* x     = (const float*)d_in[0];
    const float* W     = (const float*)d_in[1];
    const float* bias  = (const float*)d_in[2];
    const float* gamma = (const float*)d_in[3];
    const float* beta  = (const float*)d_in[4];
    float* out = (float*)d_out;

    k_zero<<<1, 64>>>();
    k_xx<<<ROWS_TOTAL / 4, 128>>>(x);
    k_hchn<<<ROWS_TOTAL / 32, 256, (128 * 17 + 32 * 16) * 16>>>(x, W, bias);
    k_topk<<<dim3(NPTS / 32, BATCH), 256,
             (32 * 16 + 128 * 17) * 16 + 128 * 4>>>(x);
    k_stats<<<ROWS_TOTAL / 32, dim3(64, 4)>>>();
    k_final<<<1, 64>>>(gamma, beta);
    k_out<<<dim3(NPTS / 64, BATCH), dim3(64, 4)>>>(out);
}